// round 14
// baseline (speedup 1.0000x reference)
#include <cuda_runtime.h>

// WOS 3x3 filter — float-key sorting network with byte-offset slots.
//
// key = (bits(mx) & ~0xFF) | (slot << 2), slot = 63-d. Sorted as float via
// FMNMX. The low byte IS the weight-table byte offset: each channel's weight
// row is 64 floats (256B) and 256B-aligned, so the LDS address is a single
// LOP3: addr = w2_base | (key & 0xFC). Ties = adjacent sorted keys sharing
// the top 24 bits (XOR < 0x100), repaired with full-precision values
// (logic proven rel_err 0.0 since R6).

#define NCH 16
#define DD 54
#define HH 64
#define WW 64
#define PIX_PER_BLK 8
#define NTHREADS 128
#define TILE_COLS (PIX_PER_BLK + 2)    // 10
#define TILE_ELEMS (3 * 3 * TILE_COLS) // 90
#define ZTOL 1e-6f

__device__ __forceinline__ unsigned smem_u32(const void* p) {
    unsigned a;
    asm("{ .reg .u64 t; cvta.to.shared.u64 t, %1; cvt.u32.u64 %0, t; }"
        : "=r"(a) : "l"(p));
    return a;
}

// weight load: addr = base | (ck & 0xFC)  -> one LOP3 + LDS
__device__ __forceinline__ float wload(unsigned base, unsigned ck) {
    unsigned a;
    asm("lop3.b32 %0, %1, 0xFC, %2, 0xEA;" : "=r"(a) : "r"(ck), "r"(base));
    float w;
    asm("ld.shared.f32 %0, [%1];" : "=f"(w) : "r"(a));
    return w;
}

__global__ __launch_bounds__(NTHREADS, 7)
void wos_kernel(const float* __restrict__ x,
                const float* __restrict__ mask,
                const float* __restrict__ weight,
                const float* __restrict__ bias,
                float* __restrict__ out)
{
    __shared__ float  tile_s[TILE_ELEMS];
    __shared__ float2 mp_s[NCH * 27];            // (mask[d0], mask[27+d0]) pairs
    __shared__ __align__(256) float w2_s[NCH * 64]; // slot-indexed weights, 256B/channel
    __shared__ float  bias_s[NCH];
    __shared__ int    toff_s[DD];
    __shared__ int    tiny_s;

    const int tid = threadIdx.x;
    const int c  = tid & (NCH - 1);
    const int ty = tid >> 4;

    const int pix0 = blockIdx.x * PIX_PER_BLK;
    const int b    = pix0 >> 12;
    const int rem  = pix0 & 4095;
    const int h    = rem >> 6;
    const int w0   = rem & 63;

    if (tid == 0) tiny_s = 0;

    // ---- cooperative staging ----
    float* mflat_all = (float*)mp_s;
    #pragma unroll
    for (int idx = tid; idx < NCH * DD; idx += NTHREADS) {
        const int cw = idx / DD;
        const int d  = idx - cw * DD;
        const float wgt = weight[idx];
        const int dst = cw * DD + ((d < 27) ? (2 * d) : (2 * d - 53));
        mflat_all[dst] = mask[idx];
        w2_s[cw * 64 + (63 - d)] = wgt;          // slot 63-d
        if (wgt <= ZTOL) tiny_s = 1;
    }
    if (tid < NCH) bias_s[tid] = bias[tid];
    if (tid < DD) {
        const int d0 = (tid < 27) ? tid : tid - 27;
        toff_s[tid] = ((d0 / 9) * 3 + ((d0 / 3) % 3)) * TILE_COLS + (d0 % 3);
    }
    #pragma unroll
    for (int idx = tid; idx < TILE_ELEMS; idx += NTHREADS) {
        int cc  = idx / (3 * TILE_COLS);
        int r   = (idx / TILE_COLS) % 3;
        int col = idx % TILE_COLS;
        int gh = h + r - 1;
        int gw = w0 + col - 1;
        float v = 0.0f;
        if (gh >= 0 && gh < HH && gw >= 0 && gw < WW)
            v = x[((b * 3 + cc) * HH + gh) * WW + gw];
        tile_s[idx] = v;
    }
    __syncthreads();

    const unsigned w2a  = smem_u32(&w2_s[c * 64]);   // 256B-aligned channel row
    const float2* mprow = &mp_s[c * 27];
    const float*  mflat = (const float*)mprow;
    const bool    tinyw = (tiny_s != 0);
    const float   bs = bias_s[c];

    // ---- build float keys (regs only); low byte = slot<<2 ----
    float key[DD];
    #pragma unroll
    for (int d0 = 0; d0 < 27; d0++) {
        const int cc = d0 / 9;
        const int r  = (d0 / 3) % 3;
        const int j  = d0 % 3;
        const float2 mm = mprow[d0];
        float t  = tile_s[(cc * 3 + r) * TILE_COLS + ty + j];
        float fp = t + mm.x;                // element d0    -> slot 63-d0
        float fm = mm.y - t;                // element 27+d0 -> slot 36-d0
        unsigned up = __float_as_uint(fp);
        unsigned um = __float_as_uint(fm);
        key[d0]      = __uint_as_float((up | 0xFFu) ^ (unsigned)(0xFF ^ ((63 - d0) << 2)));
        key[27 + d0] = __uint_as_float((um | 0xFFu) ^ (unsigned)(0xFF ^ ((36 - d0) << 2)));
    }

    // ---- Batcher odd-even merge sort, descending, n=54, FMNMX CEs ----
#define CE(A, B)                                 \
    do {                                         \
        float ka = key[A], kb = key[B];          \
        key[A] = fmaxf(ka, kb);                  \
        key[B] = fminf(ka, kb);                  \
    } while (0)

#define PASS(P, K)                                                          \
    _Pragma("unroll")                                                       \
    for (int j = (K) % (P); j + (K) < DD; j += 2 * (K)) {                   \
        _Pragma("unroll")                                                   \
        for (int i = 0; i < (K); i++) {                                     \
            const int a  = i + j;                                           \
            const int bb = i + j + (K);                                     \
            if (bb < DD && (a / (2 * (P))) == (bb / (2 * (P))))             \
                CE(a, bb);                                                  \
        }                                                                   \
    }

    PASS(1, 1)
    PASS(2, 2)  PASS(2, 1)
    PASS(4, 4)  PASS(4, 2)  PASS(4, 1)
    PASS(8, 8)  PASS(8, 4)  PASS(8, 2)  PASS(8, 1)
    PASS(16, 16) PASS(16, 8) PASS(16, 4) PASS(16, 2) PASS(16, 1)
    PASS(32, 32) PASS(32, 16) PASS(32, 8) PASS(32, 4) PASS(32, 2) PASS(32, 1)

#undef PASS
#undef CE

    // ---- tie detection: adjacent keys sharing top-24 bits ----
    unsigned t0 = 0xFFFFFFFFu, t1 = 0xFFFFFFFFu, t2 = 0xFFFFFFFFu, t3 = 0xFFFFFFFFu;
    #pragma unroll
    for (int k2 = 0; k2 + 4 <= DD - 1; k2 += 4) {
        t0 = umin(t0, __float_as_uint(key[k2])     ^ __float_as_uint(key[k2 + 1]));
        t1 = umin(t1, __float_as_uint(key[k2 + 1]) ^ __float_as_uint(key[k2 + 2]));
        t2 = umin(t2, __float_as_uint(key[k2 + 2]) ^ __float_as_uint(key[k2 + 3]));
        t3 = umin(t3, __float_as_uint(key[k2 + 3]) ^ __float_as_uint(key[k2 + 4]));
    }
    t0 = umin(t0, __float_as_uint(key[52]) ^ __float_as_uint(key[53]));
    const unsigned tmin = umin(umin(t0, t1), umin(t2, t3));
    const bool slow = __any_sync(0xFFFFFFFFu, tmin < 0x100u) | tinyw;

    float y;
    if (!slow) {
        // ---- fast path (exact): LOP3-fused weight loads ----
        float acc = 0.0f;
        unsigned selk = __float_as_uint(key[0]);
        #pragma unroll
        for (int k2 = 0; k2 < DD; k2++) {
            const unsigned ck = __float_as_uint(key[k2]);
            acc += wload(w2a, ck);
            if (acc <= bs) selk = ck;
        }
        const int d = 63 - (int)((selk >> 2) & 63u);
        const float t = tile_s[toff_s[d] + ty];
        const float m = mflat[(d < 27) ? (2 * d) : (2 * d - 53)];
        y = (d < 27) ? (t + m) : (m - t);
    } else {
        // ---- repair path: full-precision adjacent-tie repair + nz checks ----
        float acc = 0.0f, ans = 0.0f;
        bool seen = false;

        unsigned pk = __float_as_uint(key[0]);
        int dp = 63 - (int)((pk >> 2) & 63u);
        float tp = tile_s[toff_s[dp] + ty];
        float mp = mflat[(dp < 27) ? (2 * dp) : (2 * dp - 53)];
        float pv = (dp < 27) ? (tp + mp) : (mp - tp);
        float pw = wload(w2a, pk);

        #pragma unroll
        for (int k2 = 1; k2 < DD; k2++) {
            const unsigned ck = __float_as_uint(key[k2]);
            const int dc = 63 - (int)((ck >> 2) & 63u);
            const float tc = tile_s[toff_s[dc] + ty];
            const float mc = mflat[(dc < 27) ? (2 * dc) : (2 * dc - 53)];
            const float cv = (dc < 27) ? (tc + mc) : (mc - tc);
            const float cw = wload(w2a, ck);

            const bool sw = ((pk ^ ck) < 0x100u) && (cv > pv);
            const float ev = sw ? cv : pv;
            const float ew = sw ? cw : pw;
            pv = sw ? pv : cv;
            pw = sw ? pw : cw;
            pk = ck;

            const bool nz = ew > ZTOL;
            if (nz) acc += ew;
            if (nz && ((acc <= bs) || !seen)) ans = ev;
            seen |= nz;
        }
        {
            const bool nz = pw > ZTOL;
            if (nz) acc += pw;
            if (nz && ((acc <= bs) || !seen)) ans = pv;
        }
        y = ans;
    }

    // raw .view(B, NC, H, W): channel fastest -> coalesced
    const int l = h * WW + (w0 + ty);
    out[b * (NCH * HH * WW) + l * NCH + c] = y;
}

extern "C" void kernel_launch(void* const* d_in, const int* in_sizes, int n_in,
                              void* d_out, int out_size)
{
    const float* x      = (const float*)d_in[0];
    const float* mask   = (const float*)d_in[1];
    const float* weight = (const float*)d_in[2];
    const float* bias   = (const float*)d_in[3];
    float* out = (float*)d_out;

    const int B = in_sizes[0] / (3 * HH * WW);
    const int npix = B * HH * WW;
    dim3 grid(npix / PIX_PER_BLK);
    wos_kernel<<<grid, NTHREADS>>>(x, mask, weight, bias, out);
}

// round 16
// speedup vs baseline: 1.1251x; 1.1251x over previous
#include <cuda_runtime.h>

// WOS 3x3 filter — float-key sorting network (R12 semantics) with:
//  (1) single-LOP3 key build: key = (bits(mx) & ~63) | slot via
//      lop3.b32 d,a,b,c,0xEA  == (a & b) | c   (FIXED operand binding —
//      R15 crashed because a dummy "n"(0) operand displaced the slot).
//  (2) 256-thread blocks (16 pixels): mask/weight staging amortized 2x,
//      half the prologues chip-wide.
// Key format, sort network, 26-bit tie detection and both epilogues are
// byte-identical to the proven 49.3us / rel_err 0.0 kernel.

#define NCH 16
#define DD 54
#define HH 64
#define WW 64
#define PIX_PER_BLK 16
#define NTHREADS 256
#define TILE_COLS (PIX_PER_BLK + 2)    // 18
#define TILE_ELEMS (3 * 3 * TILE_COLS) // 162
#define WSTRIDE 65
#define ZTOL 1e-6f

__device__ __forceinline__ float make_key(float v, unsigned maskreg, unsigned slot) {
    unsigned k;
    asm("lop3.b32 %0, %1, %2, %3, 0xEA;"      // (a & b) | c
        : "=r"(k)
        : "r"(__float_as_uint(v)), "r"(maskreg), "r"(slot));
    return __uint_as_float(k);
}

__global__ __launch_bounds__(NTHREADS, 3)
void wos_kernel(const float* __restrict__ x,
                const float* __restrict__ mask,
                const float* __restrict__ weight,
                const float* __restrict__ bias,
                float* __restrict__ out)
{
    __shared__ float  tile_s[TILE_ELEMS];
    __shared__ float2 mp_s[NCH * 27];       // (mask[d0], mask[27+d0]) pairs
    __shared__ float  w2_s[NCH * WSTRIDE];  // slot-indexed weights
    __shared__ float  bias_s[NCH];
    __shared__ int    toff_s[DD];
    __shared__ int    tiny_s;

    const int tid = threadIdx.x;
    const int c  = tid & (NCH - 1);
    const int ty = tid >> 4;                // 0..15

    const int pix0 = blockIdx.x * PIX_PER_BLK;
    const int b    = pix0 >> 12;
    const int rem  = pix0 & 4095;
    const int h    = rem >> 6;
    const int w0   = rem & 63;              // multiple of 16

    if (tid == 0) tiny_s = 0;

    // ---- cooperative staging ----
    float* mflat_all = (float*)mp_s;
    #pragma unroll
    for (int idx = tid; idx < NCH * DD; idx += NTHREADS) {
        const int cw = idx / DD;
        const int d  = idx - cw * DD;
        const float wgt = weight[idx];
        const int dst = cw * DD + ((d < 27) ? (2 * d) : (2 * d - 53));
        mflat_all[dst] = mask[idx];
        w2_s[cw * WSTRIDE + (53 - d)] = wgt;   // slot 63-d stored at slot-10
        if (wgt <= ZTOL) tiny_s = 1;
    }
    if (tid < NCH) bias_s[tid] = bias[tid];
    if (tid < DD) {
        const int d0 = (tid < 27) ? tid : tid - 27;
        toff_s[tid] = ((d0 / 9) * 3 + ((d0 / 3) % 3)) * TILE_COLS + (d0 % 3);
    }
    #pragma unroll
    for (int idx = tid; idx < TILE_ELEMS; idx += NTHREADS) {
        int cc  = idx / (3 * TILE_COLS);
        int r   = (idx / TILE_COLS) % 3;
        int col = idx % TILE_COLS;
        int gh = h + r - 1;
        int gw = w0 + col - 1;
        float v = 0.0f;
        if (gh >= 0 && gh < HH && gw >= 0 && gw < WW)
            v = x[((b * 3 + cc) * HH + gh) * WW + gw];
        tile_s[idx] = v;
    }
    __syncthreads();

    const float*  wrow  = &w2_s[c * WSTRIDE] - 10;   // index by slot [10,63]
    const float2* mprow = &mp_s[c * 27];
    const float*  mflat = (const float*)mprow;
    const bool    tinyw = (tiny_s != 0);
    const float   bs = bias_s[c];
    const unsigned kmask = 0xFFFFFFC0u;              // in a register for LOP3

    // ---- build float keys (regs only): one LOP3 per element ----
    float key[DD];
    #pragma unroll
    for (int d0 = 0; d0 < 27; d0++) {
        const int cc = d0 / 9;
        const int r  = (d0 / 3) % 3;
        const int j  = d0 % 3;
        const float2 mm = mprow[d0];
        float t  = tile_s[(cc * 3 + r) * TILE_COLS + ty + j];
        float fp = t + mm.x;                // element d0    -> slot 63-d0
        float fm = mm.y - t;                // element 27+d0 -> slot 36-d0
        key[d0]      = make_key(fp, kmask, (unsigned)(63 - d0));
        key[27 + d0] = make_key(fm, kmask, (unsigned)(36 - d0));
    }

    // ---- Batcher odd-even merge sort, descending, n=54, FMNMX CEs ----
#define CE(A, B)                                 \
    do {                                         \
        float ka = key[A], kb = key[B];          \
        key[A] = fmaxf(ka, kb);                  \
        key[B] = fminf(ka, kb);                  \
    } while (0)

#define PASS(P, K)                                                          \
    _Pragma("unroll")                                                       \
    for (int j = (K) % (P); j + (K) < DD; j += 2 * (K)) {                   \
        _Pragma("unroll")                                                   \
        for (int i = 0; i < (K); i++) {                                     \
            const int a  = i + j;                                           \
            const int bb = i + j + (K);                                     \
            if (bb < DD && (a / (2 * (P))) == (bb / (2 * (P))))             \
                CE(a, bb);                                                  \
        }                                                                   \
    }

    PASS(1, 1)
    PASS(2, 2)  PASS(2, 1)
    PASS(4, 4)  PASS(4, 2)  PASS(4, 1)
    PASS(8, 8)  PASS(8, 4)  PASS(8, 2)  PASS(8, 1)
    PASS(16, 16) PASS(16, 8) PASS(16, 4) PASS(16, 2) PASS(16, 1)
    PASS(32, 32) PASS(32, 16) PASS(32, 8) PASS(32, 4) PASS(32, 2) PASS(32, 1)

#undef PASS
#undef CE

    // ---- tie detection: adjacent keys sharing top-26 bits ----
    unsigned t0 = 0xFFFFFFFFu, t1 = 0xFFFFFFFFu, t2 = 0xFFFFFFFFu, t3 = 0xFFFFFFFFu;
    #pragma unroll
    for (int k2 = 0; k2 + 4 <= DD - 1; k2 += 4) {
        t0 = umin(t0, __float_as_uint(key[k2])     ^ __float_as_uint(key[k2 + 1]));
        t1 = umin(t1, __float_as_uint(key[k2 + 1]) ^ __float_as_uint(key[k2 + 2]));
        t2 = umin(t2, __float_as_uint(key[k2 + 2]) ^ __float_as_uint(key[k2 + 3]));
        t3 = umin(t3, __float_as_uint(key[k2 + 3]) ^ __float_as_uint(key[k2 + 4]));
    }
    t0 = umin(t0, __float_as_uint(key[52]) ^ __float_as_uint(key[53]));
    const unsigned tmin = umin(umin(t0, t1), umin(t2, t3));
    const bool slow = __any_sync(0xFFFFFFFFu, tmin < 64u) | tinyw;

    float y;
    if (!slow) {
        // ---- fast path (exact): weights only; recompute 1 value at end ----
        float acc = 0.0f;
        unsigned selk = __float_as_uint(key[0]);
        #pragma unroll
        for (int k2 = 0; k2 < DD; k2++) {
            const unsigned ck = __float_as_uint(key[k2]);
            acc += wrow[ck & 63u];
            if (acc <= bs) selk = ck;
        }
        const int d = 63 - (int)(selk & 63u);
        const float t = tile_s[toff_s[d] + ty];
        const float m = mflat[(d < 27) ? (2 * d) : (2 * d - 53)];
        y = (d < 27) ? (t + m) : (m - t);
    } else {
        // ---- repair path: full-precision adjacent-tie repair + nz checks ----
        float acc = 0.0f, ans = 0.0f;
        bool seen = false;

        unsigned pk = __float_as_uint(key[0]);
        int dp = 63 - (int)(pk & 63u);
        float tp = tile_s[toff_s[dp] + ty];
        float mp = mflat[(dp < 27) ? (2 * dp) : (2 * dp - 53)];
        float pv = (dp < 27) ? (tp + mp) : (mp - tp);
        float pw = wrow[pk & 63u];

        #pragma unroll
        for (int k2 = 1; k2 < DD; k2++) {
            const unsigned ck = __float_as_uint(key[k2]);
            const unsigned sl = ck & 63u;
            const int dc = 63 - (int)sl;
            const float tc = tile_s[toff_s[dc] + ty];
            const float mc = mflat[(dc < 27) ? (2 * dc) : (2 * dc - 53)];
            const float cv = (dc < 27) ? (tc + mc) : (mc - tc);
            const float cw = wrow[sl];

            const bool sw = ((pk ^ ck) < 64u) && (cv > pv);
            const float ev = sw ? cv : pv;
            const float ew = sw ? cw : pw;
            pv = sw ? pv : cv;
            pw = sw ? pw : cw;
            pk = ck;

            const bool nz = ew > ZTOL;
            if (nz) acc += ew;
            if (nz && ((acc <= bs) || !seen)) ans = ev;
            seen |= nz;
        }
        {
            const bool nz = pw > ZTOL;
            if (nz) acc += pw;
            if (nz && ((acc <= bs) || !seen)) ans = pv;
        }
        y = ans;
    }

    // raw .view(B, NC, H, W): channel fastest -> coalesced
    const int l = h * WW + (w0 + ty);
    out[b * (NCH * HH * WW) + l * NCH + c] = y;
}

extern "C" void kernel_launch(void* const* d_in, const int* in_sizes, int n_in,
                              void* d_out, int out_size)
{
    const float* x      = (const float*)d_in[0];
    const float* mask   = (const float*)d_in[1];
    const float* weight = (const float*)d_in[2];
    const float* bias   = (const float*)d_in[3];
    float* out = (float*)d_out;

    const int B = in_sizes[0] / (3 * HH * WW);
    const int npix = B * HH * WW;
    dim3 grid(npix / PIX_PER_BLK);
    wos_kernel<<<grid, NTHREADS>>>(x, mask, weight, bias, out);
}

// round 17
// speedup vs baseline: 1.1664x; 1.0368x over previous
#include <cuda_runtime.h>

// WOS 3x3 filter — float-key sorting network. Consolidation round:
//  - single-LOP3 key build (validated in R16: -8% alu ops)
//  - R12 launch shape (128 thr, 8 px/block, 7 blocks/SM: best occ/issue)
// Key format, sort network, 26-bit tie detection, fast/repair epilogues
// byte-identical to the proven 49.3us / rel_err 0.0 kernel.

#define NCH 16
#define DD 54
#define HH 64
#define WW 64
#define PIX_PER_BLK 8
#define NTHREADS 128
#define TILE_COLS (PIX_PER_BLK + 2)    // 10
#define TILE_ELEMS (3 * 3 * TILE_COLS) // 90
#define WSTRIDE 65
#define ZTOL 1e-6f

__device__ __forceinline__ float make_key(float v, unsigned maskreg, unsigned slot) {
    unsigned k;
    asm("lop3.b32 %0, %1, %2, %3, 0xEA;"      // (a & b) | c
        : "=r"(k)
        : "r"(__float_as_uint(v)), "r"(maskreg), "r"(slot));
    return __uint_as_float(k);
}

__global__ __launch_bounds__(NTHREADS, 7)
void wos_kernel(const float* __restrict__ x,
                const float* __restrict__ mask,
                const float* __restrict__ weight,
                const float* __restrict__ bias,
                float* __restrict__ out)
{
    __shared__ float  tile_s[TILE_ELEMS];
    __shared__ float2 mp_s[NCH * 27];       // (mask[d0], mask[27+d0]) pairs
    __shared__ float  w2_s[NCH * WSTRIDE];  // slot-indexed weights
    __shared__ float  bias_s[NCH];
    __shared__ int    toff_s[DD];
    __shared__ int    tiny_s;

    const int tid = threadIdx.x;
    const int c  = tid & (NCH - 1);
    const int ty = tid >> 4;                // 0..7

    const int pix0 = blockIdx.x * PIX_PER_BLK;
    const int b    = pix0 >> 12;
    const int rem  = pix0 & 4095;
    const int h    = rem >> 6;
    const int w0   = rem & 63;

    if (tid == 0) tiny_s = 0;

    // ---- cooperative staging ----
    float* mflat_all = (float*)mp_s;
    #pragma unroll
    for (int idx = tid; idx < NCH * DD; idx += NTHREADS) {
        const int cw = idx / DD;
        const int d  = idx - cw * DD;
        const float wgt = weight[idx];
        const int dst = cw * DD + ((d < 27) ? (2 * d) : (2 * d - 53));
        mflat_all[dst] = mask[idx];
        w2_s[cw * WSTRIDE + (53 - d)] = wgt;   // slot 63-d stored at slot-10
        if (wgt <= ZTOL) tiny_s = 1;
    }
    if (tid < NCH) bias_s[tid] = bias[tid];
    if (tid < DD) {
        const int d0 = (tid < 27) ? tid : tid - 27;
        toff_s[tid] = ((d0 / 9) * 3 + ((d0 / 3) % 3)) * TILE_COLS + (d0 % 3);
    }
    #pragma unroll
    for (int idx = tid; idx < TILE_ELEMS; idx += NTHREADS) {
        int cc  = idx / (3 * TILE_COLS);
        int r   = (idx / TILE_COLS) % 3;
        int col = idx % TILE_COLS;
        int gh = h + r - 1;
        int gw = w0 + col - 1;
        float v = 0.0f;
        if (gh >= 0 && gh < HH && gw >= 0 && gw < WW)
            v = x[((b * 3 + cc) * HH + gh) * WW + gw];
        tile_s[idx] = v;
    }
    __syncthreads();

    const float*  wrow  = &w2_s[c * WSTRIDE] - 10;   // index by slot [10,63]
    const float2* mprow = &mp_s[c * 27];
    const float*  mflat = (const float*)mprow;
    const bool    tinyw = (tiny_s != 0);
    const float   bs = bias_s[c];
    const unsigned kmask = 0xFFFFFFC0u;              // in a register for LOP3

    // ---- build float keys (regs only): one LOP3 per element ----
    float key[DD];
    #pragma unroll
    for (int d0 = 0; d0 < 27; d0++) {
        const int cc = d0 / 9;
        const int r  = (d0 / 3) % 3;
        const int j  = d0 % 3;
        const float2 mm = mprow[d0];
        float t  = tile_s[(cc * 3 + r) * TILE_COLS + ty + j];
        float fp = t + mm.x;                // element d0    -> slot 63-d0
        float fm = mm.y - t;                // element 27+d0 -> slot 36-d0
        key[d0]      = make_key(fp, kmask, (unsigned)(63 - d0));
        key[27 + d0] = make_key(fm, kmask, (unsigned)(36 - d0));
    }

    // ---- Batcher odd-even merge sort, descending, n=54, FMNMX CEs ----
#define CE(A, B)                                 \
    do {                                         \
        float ka = key[A], kb = key[B];          \
        key[A] = fmaxf(ka, kb);                  \
        key[B] = fminf(ka, kb);                  \
    } while (0)

#define PASS(P, K)                                                          \
    _Pragma("unroll")                                                       \
    for (int j = (K) % (P); j + (K) < DD; j += 2 * (K)) {                   \
        _Pragma("unroll")                                                   \
        for (int i = 0; i < (K); i++) {                                     \
            const int a  = i + j;                                           \
            const int bb = i + j + (K);                                     \
            if (bb < DD && (a / (2 * (P))) == (bb / (2 * (P))))             \
                CE(a, bb);                                                  \
        }                                                                   \
    }

    PASS(1, 1)
    PASS(2, 2)  PASS(2, 1)
    PASS(4, 4)  PASS(4, 2)  PASS(4, 1)
    PASS(8, 8)  PASS(8, 4)  PASS(8, 2)  PASS(8, 1)
    PASS(16, 16) PASS(16, 8) PASS(16, 4) PASS(16, 2) PASS(16, 1)
    PASS(32, 32) PASS(32, 16) PASS(32, 8) PASS(32, 4) PASS(32, 2) PASS(32, 1)

#undef PASS
#undef CE

    // ---- tie detection: adjacent keys sharing top-26 bits ----
    unsigned t0 = 0xFFFFFFFFu, t1 = 0xFFFFFFFFu, t2 = 0xFFFFFFFFu, t3 = 0xFFFFFFFFu;
    #pragma unroll
    for (int k2 = 0; k2 + 4 <= DD - 1; k2 += 4) {
        t0 = umin(t0, __float_as_uint(key[k2])     ^ __float_as_uint(key[k2 + 1]));
        t1 = umin(t1, __float_as_uint(key[k2 + 1]) ^ __float_as_uint(key[k2 + 2]));
        t2 = umin(t2, __float_as_uint(key[k2 + 2]) ^ __float_as_uint(key[k2 + 3]));
        t3 = umin(t3, __float_as_uint(key[k2 + 3]) ^ __float_as_uint(key[k2 + 4]));
    }
    t0 = umin(t0, __float_as_uint(key[52]) ^ __float_as_uint(key[53]));
    const unsigned tmin = umin(umin(t0, t1), umin(t2, t3));
    const bool slow = __any_sync(0xFFFFFFFFu, tmin < 64u) | tinyw;

    float y;
    if (!slow) {
        // ---- fast path (exact): weights only; recompute 1 value at end ----
        float acc = 0.0f;
        unsigned selk = __float_as_uint(key[0]);
        #pragma unroll
        for (int k2 = 0; k2 < DD; k2++) {
            const unsigned ck = __float_as_uint(key[k2]);
            acc += wrow[ck & 63u];
            if (acc <= bs) selk = ck;
        }
        const int d = 63 - (int)(selk & 63u);
        const float t = tile_s[toff_s[d] + ty];
        const float m = mflat[(d < 27) ? (2 * d) : (2 * d - 53)];
        y = (d < 27) ? (t + m) : (m - t);
    } else {
        // ---- repair path: full-precision adjacent-tie repair + nz checks ----
        float acc = 0.0f, ans = 0.0f;
        bool seen = false;

        unsigned pk = __float_as_uint(key[0]);
        int dp = 63 - (int)(pk & 63u);
        float tp = tile_s[toff_s[dp] + ty];
        float mp = mflat[(dp < 27) ? (2 * dp) : (2 * dp - 53)];
        float pv = (dp < 27) ? (tp + mp) : (mp - tp);
        float pw = wrow[pk & 63u];

        #pragma unroll
        for (int k2 = 1; k2 < DD; k2++) {
            const unsigned ck = __float_as_uint(key[k2]);
            const unsigned sl = ck & 63u;
            const int dc = 63 - (int)sl;
            const float tc = tile_s[toff_s[dc] + ty];
            const float mc = mflat[(dc < 27) ? (2 * dc) : (2 * dc - 53)];
            const float cv = (dc < 27) ? (tc + mc) : (mc - tc);
            const float cw = wrow[sl];

            const bool sw = ((pk ^ ck) < 64u) && (cv > pv);
            const float ev = sw ? cv : pv;
            const float ew = sw ? cw : pw;
            pv = sw ? pv : cv;
            pw = sw ? pw : cw;
            pk = ck;

            const bool nz = ew > ZTOL;
            if (nz) acc += ew;
            if (nz && ((acc <= bs) || !seen)) ans = ev;
            seen |= nz;
        }
        {
            const bool nz = pw > ZTOL;
            if (nz) acc += pw;
            if (nz && ((acc <= bs) || !seen)) ans = pv;
        }
        y = ans;
    }

    // raw .view(B, NC, H, W): channel fastest -> coalesced
    const int l = h * WW + (w0 + ty);
    out[b * (NCH * HH * WW) + l * NCH + c] = y;
}

extern "C" void kernel_launch(void* const* d_in, const int* in_sizes, int n_in,
                              void* d_out, int out_size)
{
    const float* x      = (const float*)d_in[0];
    const float* mask   = (const float*)d_in[1];
    const float* weight = (const float*)d_in[2];
    const float* bias   = (const float*)d_in[3];
    float* out = (float*)d_out;

    const int B = in_sizes[0] / (3 * HH * WW);
    const int npix = B * HH * WW;
    dim3 grid(npix / PIX_PER_BLK);
    wos_kernel<<<grid, NTHREADS>>>(x, mask, weight, bias, out);
}